// round 3
// baseline (speedup 1.0000x reference)
#include <cuda_runtime.h>

// ---------------------------------------------------------------------------
// DASAttentionGate: dwconv3x3 -> pwconv1x1 -> InstanceNorm -> offset conv3x3
//                   -> deformable conv3x3 -> LayerNorm(C) -> sigmoid -> gate
// B=4, C=O=128, H=W=96. All fp32.
// ---------------------------------------------------------------------------

#define Bc   4
#define Cc   128
#define Hc   96
#define Wc   96
#define HW   9216            // Hc*Wc
#define PIX  36864           // Bc*HW
#define KTAP 9
#define KKc  1152            // Cc*KTAP

// -------------------- device scratch (no allocations allowed) --------------
__device__ float g_h1[PIX * Cc];          // dw conv out, NCHW
__device__ float g_h2[PIX * Cc];          // pw conv out, NHWC [pix][c]
__device__ float g_dsc[PIX * Cc];         // instance-normed, NHWC [pix][c]
__device__ float g_stats[1024];           // sum[512], sumsq[512]  (b*128+c)
__device__ float g_mr[1024];              // mean[512], rstd[512]
__device__ float g_off[PIX * 18];         // offsets, [pix][18]
__device__ float g_offwT[9 * 18 * 128];   // offset weights [k][j][c]
__device__ float g_pwT[128 * 128];        // pw weights [c][o]
__device__ float g_wT[KKc * 128];         // deform weights [k*128+c][o]
__device__ float g_samp[PIX * KKc];       // gathered samples [pix][k*128+c]
__device__ float g_dc[PIX * Cc];          // deform conv out, [pix][o]

// -------------------- prep: weight transposes + zero stats -----------------
__global__ void prep_kernel(const float* __restrict__ dc_w,
                            const float* __restrict__ pw_w,
                            const float* __restrict__ off_w) {
    int i = blockIdx.x * blockDim.x + threadIdx.x;
    if (i < KKc * 128) {
        int kk = i >> 7, o = i & 127;
        int k = kk >> 7, c = kk & 127;
        g_wT[i] = dc_w[(o * 128 + c) * 9 + k];
    }
    if (i < 128 * 128) {
        int c = i >> 7, o = i & 127;
        g_pwT[i] = pw_w[o * 128 + c];
    }
    if (i < 9 * 18 * 128) {
        int k = i / 2304;
        int r = i - k * 2304;
        int j = r >> 7, c = r & 127;
        g_offwT[i] = off_w[(j * 128 + c) * 9 + k];
    }
    if (i < 1024) g_stats[i] = 0.f;
}

// -------------------- depthwise 3x3 conv (NCHW -> NCHW) --------------------
__global__ void dw_kernel(const float* __restrict__ x,
                          const float* __restrict__ dw_w,
                          const float* __restrict__ dw_b) {
    int i = blockIdx.x * blockDim.x + threadIdx.x;
    if (i >= PIX * Cc) return;
    int xw = i % Wc;
    int y  = (i / Wc) % Hc;
    int c  = (i / HW) % Cc;
    int b  = i / (HW * Cc);
    const float* xin = x + (size_t)(b * Cc + c) * HW;
    float acc = dw_b[c];
#pragma unroll
    for (int ky = 0; ky < 3; ky++) {
        int yy = y + ky - 1;
        if ((unsigned)yy >= Hc) continue;
#pragma unroll
        for (int kx = 0; kx < 3; kx++) {
            int xx = xw + kx - 1;
            if ((unsigned)xx >= Wc) continue;
            acc += dw_w[c * 9 + ky * 3 + kx] * xin[yy * Wc + xx];
        }
    }
    g_h1[i] = acc;
}

// -------------------- pointwise 1x1 conv: NCHW -> NHWC ---------------------
// Block = 32 pixels x 128 out-channels, 256 threads, 4x4 microtile.
__global__ void pw_kernel(const float* __restrict__ pw_b) {
    __shared__ float sS[Cc * 32];     // [c][px]
    int t  = threadIdx.x;
    int p0 = blockIdx.x * 32;
    int b  = p0 / HW;
    int s0 = p0 - b * HW;
    const float* src = g_h1 + (size_t)b * Cc * HW + s0;
    for (int i = t; i < Cc * 32; i += 256) {
        int c = i >> 5, px = i & 31;
        sS[i] = src[c * HW + px];
    }
    __syncthreads();
    int px0 = (t & 7) * 4;
    int o0  = (t >> 3) * 4;
    float acc[4][4];
#pragma unroll
    for (int p = 0; p < 4; p++)
#pragma unroll
        for (int q = 0; q < 4; q++) acc[p][q] = 0.f;
#pragma unroll 4
    for (int c = 0; c < 128; c++) {
        float4 sv = *(const float4*)&sS[c * 32 + px0];
        float4 wv = __ldg((const float4*)&g_pwT[c * 128 + o0]);
        float sm[4] = {sv.x, sv.y, sv.z, sv.w};
        float wm[4] = {wv.x, wv.y, wv.z, wv.w};
#pragma unroll
        for (int p = 0; p < 4; p++)
#pragma unroll
            for (int q = 0; q < 4; q++) acc[p][q] += sm[p] * wm[q];
    }
    float bb[4];
#pragma unroll
    for (int q = 0; q < 4; q++) bb[q] = pw_b[o0 + q];
#pragma unroll
    for (int p = 0; p < 4; p++) {
        float4 o;
        o.x = acc[p][0] + bb[0];
        o.y = acc[p][1] + bb[1];
        o.z = acc[p][2] + bb[2];
        o.w = acc[p][3] + bb[3];
        *(float4*)&g_h2[(size_t)(p0 + px0 + p) * 128 + o0] = o;
    }
}

// -------------------- instance-norm stats ----------------------------------
__global__ void stats_kernel() {
    int t = threadIdx.x;
    int r = blockIdx.x;                 // (b, y)
    int b = r / Hc, y = r % Hc;
    const float* p = g_h2 + (size_t)(b * HW + y * Wc) * 128 + t;
    float s = 0.f, s2 = 0.f;
    for (int x = 0; x < Wc; x++) {
        float v = p[x * 128];
        s += v; s2 += v * v;
    }
    atomicAdd(&g_stats[b * 128 + t], s);
    atomicAdd(&g_stats[512 + b * 128 + t], s2);
}

__global__ void mr_kernel() {
    int i = blockIdx.x * blockDim.x + threadIdx.x;
    if (i >= 512) return;
    float m = g_stats[i] * (1.f / HW);
    float v = g_stats[512 + i] * (1.f / HW) - m * m;
    g_mr[i] = m;
    g_mr[512 + i] = rsqrtf(v + 1e-5f);
}

__global__ void norm_kernel() {
    int i = blockIdx.x * blockDim.x + threadIdx.x;
    if (i >= PIX * Cc) return;
    int c  = i & 127;
    int pg = i >> 7;
    int b  = pg / HW;
    int bc = b * 128 + c;
    g_dsc[i] = (g_h2[i] - g_mr[bc]) * g_mr[512 + bc];
}

// -------------------- offset conv 3x3 (Cout = 18) --------------------------
// 256 threads = 8 warps; each warp handles 4 pixels, lanes partition channels.
__global__ __launch_bounds__(256) void off_kernel(const float* __restrict__ off_b) {
    extern __shared__ float w_s[];        // [k][j][c] = 20736 floats
    for (int i = threadIdx.x; i < 9 * 18 * 128; i += 256) w_s[i] = g_offwT[i];
    __syncthreads();

    int warp = threadIdx.x >> 5, lane = threadIdx.x & 31;
    int pg0  = blockIdx.x * 32 + warp * 4;
    int b    = pg0 / HW;
    const float* img = g_dsc + (size_t)b * HW * 128;
    int yb[4], xb[4];
#pragma unroll
    for (int p = 0; p < 4; p++) {
        int s = pg0 + p - b * HW;
        yb[p] = s / Wc; xb[p] = s % Wc;
    }
    int c0 = lane * 4;
    float acc[4][18];
#pragma unroll
    for (int p = 0; p < 4; p++)
#pragma unroll
        for (int j = 0; j < 18; j++) acc[p][j] = 0.f;

#pragma unroll
    for (int k = 0; k < 9; k++) {
        int dy = k / 3 - 1, dx = k % 3 - 1;
        float4 v[4];
#pragma unroll
        for (int p = 0; p < 4; p++) {
            int yy = yb[p] + dy, xx = xb[p] + dx;
            if ((unsigned)yy < Hc && (unsigned)xx < Wc)
                v[p] = *(const float4*)&img[(size_t)(yy * Wc + xx) * 128 + c0];
            else
                v[p] = make_float4(0.f, 0.f, 0.f, 0.f);
        }
        const float* wb = w_s + k * 2304;
#pragma unroll
        for (int j = 0; j < 18; j++) {
            float4 wv = *(const float4*)&wb[j * 128 + c0];
#pragma unroll
            for (int p = 0; p < 4; p++)
                acc[p][j] += wv.x * v[p].x + wv.y * v[p].y + wv.z * v[p].z + wv.w * v[p].w;
        }
    }
#pragma unroll
    for (int p = 0; p < 4; p++) {
        float keep = 0.f;
#pragma unroll
        for (int j = 0; j < 18; j++) {
            float r = acc[p][j];
            r += __shfl_xor_sync(0xffffffffu, r, 16);
            r += __shfl_xor_sync(0xffffffffu, r, 8);
            r += __shfl_xor_sync(0xffffffffu, r, 4);
            r += __shfl_xor_sync(0xffffffffu, r, 2);
            r += __shfl_xor_sync(0xffffffffu, r, 1);
            if (lane == j) keep = r;
        }
        if (lane < 18) g_off[(size_t)(pg0 + p) * 18 + lane] = keep + off_b[lane];
    }
}

// -------------------- bilinear gather (im2col for deform conv) -------------
__device__ __forceinline__ void sample_corner(const float* img, int c0,
                                              float yf, float xf, float w,
                                              float4& acc) {
    if (yf >= 0.f && yf <= (float)(Hc - 1) && xf >= 0.f && xf <= (float)(Wc - 1)) {
        int yi = (int)yf, xi = (int)xf;
        float4 v = *(const float4*)&img[(size_t)(yi * Wc + xi) * 128 + c0];
        acc.x += w * v.x; acc.y += w * v.y; acc.z += w * v.z; acc.w += w * v.w;
    }
}

__global__ __launch_bounds__(256) void gather_kernel() {
    int warp = threadIdx.x >> 5, lane = threadIdx.x & 31;
    int pg = blockIdx.x * 8 + warp;
    int b  = pg / HW;
    int s  = pg - b * HW;
    int y  = s / Wc, xw = s % Wc;
    const float* img  = g_dsc + (size_t)b * HW * 128;
    const float* op   = g_off + (size_t)pg * 18;
    float*       outp = g_samp + (size_t)pg * KKc;
    int c0 = lane * 4;
#pragma unroll
    for (int k = 0; k < 9; k++) {
        float ys = (float)(y + (k / 3) - 1) + op[2 * k];
        float xs = (float)(xw + (k % 3) - 1) + op[2 * k + 1];
        float y0 = floorf(ys), x0 = floorf(xs);
        float wy = ys - y0, wx = xs - x0;
        float4 acc = make_float4(0.f, 0.f, 0.f, 0.f);
        sample_corner(img, c0, y0,       x0,       (1.f - wy) * (1.f - wx), acc);
        sample_corner(img, c0, y0,       x0 + 1.f, (1.f - wy) * wx,         acc);
        sample_corner(img, c0, y0 + 1.f, x0,       wy * (1.f - wx),         acc);
        sample_corner(img, c0, y0 + 1.f, x0 + 1.f, wy * wx,                 acc);
        *(float4*)&outp[k * 128 + c0] = acc;
    }
}

// -------------------- deform conv GEMM: [36864 x 1152] * [1152 x 128] ------
// BM=64, BN=128, BK=16, 256 threads, 4x8 microtile.
__global__ __launch_bounds__(256) void gemm_kernel(const float* __restrict__ dc_b) {
    __shared__ float As[16 * 64];    // [kk][m]
    __shared__ float Bs[16 * 128];   // [kk][o]
    int t  = threadIdx.x;
    int m0 = blockIdx.x * 64;

    int lm  = t >> 2;            // 0..63
    int lk4 = (t & 3) * 4;       // 0,4,8,12
    int bk  = t >> 4;            // 0..15
    int bo  = (t & 15) * 8;      // 0..120

    int tm0 = (t & 15) * 4;      // 0..60
    int to0 = (t >> 4) * 8;      // 0..120

    float acc[4][8];
#pragma unroll
    for (int i = 0; i < 4; i++)
#pragma unroll
        for (int j = 0; j < 8; j++) acc[i][j] = 0.f;

    for (int k0 = 0; k0 < KKc; k0 += 16) {
        float4 a  = *(const float4*)&g_samp[(size_t)(m0 + lm) * KKc + k0 + lk4];
        float4 b0 = *(const float4*)&g_wT[(size_t)(k0 + bk) * 128 + bo];
        float4 b1 = *(const float4*)&g_wT[(size_t)(k0 + bk) * 128 + bo + 4];
        As[(lk4 + 0) * 64 + lm] = a.x;
        As[(lk4 + 1) * 64 + lm] = a.y;
        As[(lk4 + 2) * 64 + lm] = a.z;
        As[(lk4 + 3) * 64 + lm] = a.w;
        *(float4*)&Bs[bk * 128 + bo]     = b0;
        *(float4*)&Bs[bk * 128 + bo + 4] = b1;
        __syncthreads();
#pragma unroll
        for (int kk = 0; kk < 16; kk++) {
            float4 av  = *(const float4*)&As[kk * 64 + tm0];
            float4 bv0 = *(const float4*)&Bs[kk * 128 + to0];
            float4 bv1 = *(const float4*)&Bs[kk * 128 + to0 + 4];
            float am[4] = {av.x, av.y, av.z, av.w};
            float bn[8] = {bv0.x, bv0.y, bv0.z, bv0.w, bv1.x, bv1.y, bv1.z, bv1.w};
#pragma unroll
            for (int i = 0; i < 4; i++)
#pragma unroll
                for (int j = 0; j < 8; j++) acc[i][j] += am[i] * bn[j];
        }
        __syncthreads();
    }
    float bb[8];
#pragma unroll
    for (int j = 0; j < 8; j++) bb[j] = dc_b[to0 + j];
#pragma unroll
    for (int i = 0; i < 4; i++) {
        int m = m0 + tm0 + i;
        float4 o0v, o1v;
        o0v.x = acc[i][0] + bb[0]; o0v.y = acc[i][1] + bb[1];
        o0v.z = acc[i][2] + bb[2]; o0v.w = acc[i][3] + bb[3];
        o1v.x = acc[i][4] + bb[4]; o1v.y = acc[i][5] + bb[5];
        o1v.z = acc[i][6] + bb[6]; o1v.w = acc[i][7] + bb[7];
        *(float4*)&g_dc[(size_t)m * 128 + to0]     = o0v;
        *(float4*)&g_dc[(size_t)m * 128 + to0 + 4] = o1v;
    }
}

// -------------------- LayerNorm(C) + sigmoid gate, NHWC -> NCHW ------------
__global__ __launch_bounds__(128) void final_kernel(const float* __restrict__ ln_g,
                                                    const float* __restrict__ ln_b,
                                                    float* __restrict__ out) {
    __shared__ float sout[128 * 33];
    __shared__ float red[8];
    int t = threadIdx.x;
    int lane = t & 31, wid = t >> 5;
    int bid = blockIdx.x;
    int b = bid / 288;
    int r = bid - b * 288;
    int y = r / 3;
    int x0 = (r % 3) * 32;
    int pgbase = b * HW + y * Wc + x0;
    float gv = ln_g[t], bvv = ln_b[t];

    for (int px = 0; px < 32; px++) {
        int pg = pgbase + px;
        float v = g_dc[(size_t)pg * 128 + t];
        float s = v, s2 = v * v;
#pragma unroll
        for (int o = 16; o; o >>= 1) {
            s  += __shfl_xor_sync(0xffffffffu, s,  o);
            s2 += __shfl_xor_sync(0xffffffffu, s2, o);
        }
        if (lane == 0) { red[wid] = s; red[4 + wid] = s2; }
        __syncthreads();
        float sum = red[0] + red[1] + red[2] + red[3];
        float sq  = red[4] + red[5] + red[6] + red[7];
        float mean = sum * (1.f / 128.f);
        float var  = sq * (1.f / 128.f) - mean * mean;
        float rstd = rsqrtf(var + 1e-5f);
        float ln   = (v - mean) * rstd * gv + bvv;
        float attn = 1.f / (1.f + expf(-ln));
        sout[t * 33 + px] = g_dsc[(size_t)pg * 128 + t] * attn;
        __syncthreads();
    }
    // transpose write NHWC -> NCHW, coalesced
    for (int j = 0; j < 32; j++) {
        int flat = j * 128 + t;
        int c = flat >> 5, px = flat & 31;
        out[(size_t)(b * 128 + c) * HW + y * Wc + x0 + px] = sout[c * 33 + px];
    }
}

// ---------------------------------------------------------------------------
extern "C" void kernel_launch(void* const* d_in, const int* in_sizes, int n_in,
                              void* d_out, int out_size) {
    const float* x    = (const float*)d_in[0];
    const float* dw_w = (const float*)d_in[1];
    const float* dw_b = (const float*)d_in[2];
    const float* pw_w = (const float*)d_in[3];
    const float* pw_b = (const float*)d_in[4];
    const float* off_w = (const float*)d_in[5];
    const float* off_b = (const float*)d_in[6];
    const float* dc_w = (const float*)d_in[7];
    const float* dc_b = (const float*)d_in[8];
    const float* ln_g = (const float*)d_in[9];
    const float* ln_b = (const float*)d_in[10];
    float* out = (float*)d_out;

    cudaFuncSetAttribute(off_kernel, cudaFuncAttributeMaxDynamicSharedMemorySize,
                         9 * 18 * 128 * 4);

    prep_kernel<<<576, 256>>>(dc_w, pw_w, off_w);
    dw_kernel<<<18432, 256>>>(x, dw_w, dw_b);
    pw_kernel<<<1152, 256>>>(pw_b);
    stats_kernel<<<384, 128>>>();
    mr_kernel<<<2, 256>>>();
    norm_kernel<<<18432, 256>>>();
    off_kernel<<<1152, 256, 9 * 18 * 128 * 4>>>(off_b);
    gather_kernel<<<4608, 256>>>();
    gemm_kernel<<<576, 256>>>(dc_b);
    final_kernel<<<1152, 128>>>(ln_g, ln_b, out);
}